// round 1
// baseline (speedup 1.0000x reference)
#include <cuda_runtime.h>
#include <cuda_bf16.h>

// LightGCN on GB300.
// Pipeline:
//   1) init: bufA = concat(user_emb, item_emb); acc = bufA; bufB = 0
//   2) 3x { spmm: buf_dst[row] += val * buf_src[col]  (edge-parallel, vector RED)
//           fuse: acc += buf_dst; zero buf_src (next layer's target) }
//   3) dot: gamma[b] = dot(acc[u], acc[N_USERS+i]) / (LAYERS+1)^2
//
// Embedding table (38.4 MB) fits in L2, so SpMM gather/scatter is L2-resident.

#define N_USERS 100000
#define M_ITEMS 50000
#define NN      (N_USERS + M_ITEMS)   // 150000
#define DVEC    16                    // D=64 floats = 16 float4
#define INV_SCALE (1.0f / 16.0f)      // 1/(LAYERS+1)^2 = 1/16

// Static device scratch (allocation-free per harness rules). 3 x 38.4 MB.
__device__ float4 g_emb[2][NN * DVEC];
__device__ float4 g_acc[NN * DVEC];

// ---------------------------------------------------------------------------
// init: bufA = all_emb, acc = all_emb, bufB = 0
// ---------------------------------------------------------------------------
__global__ void lgcn_init(const float* __restrict__ user_emb,
                          const float* __restrict__ item_emb) {
    int i = blockIdx.x * blockDim.x + threadIdx.x;   // float4 index
    if (i >= NN * DVEC) return;
    float4 v;
    if (i < N_USERS * DVEC) {
        v = reinterpret_cast<const float4*>(user_emb)[i];
    } else {
        v = reinterpret_cast<const float4*>(item_emb)[i - N_USERS * DVEC];
    }
    g_emb[0][i] = v;
    g_acc[i]    = v;
    g_emb[1][i] = make_float4(0.f, 0.f, 0.f, 0.f);
}

// ---------------------------------------------------------------------------
// SpMM: edge-parallel. 16 threads per edge, one float4 per thread.
// dst[row] += val * src[col]  via red.global.add.v4.f32
// ---------------------------------------------------------------------------
__device__ __forceinline__ void red_add_v4(float4* p, float4 m) {
    asm volatile(
        "{\n\t"
        ".reg .u64 a;\n\t"
        "cvta.to.global.u64 a, %0;\n\t"
        "red.global.add.v4.f32 [a], {%1, %2, %3, %4};\n\t"
        "}"
        :: "l"(p), "f"(m.x), "f"(m.y), "f"(m.z), "f"(m.w)
        : "memory");
}

__global__ void lgcn_spmm(const int*   __restrict__ rows,
                          const int*   __restrict__ cols,
                          const float* __restrict__ vals,
                          int E, int src, int dst) {
    long long t = (long long)blockIdx.x * blockDim.x + threadIdx.x;
    int e = (int)(t >> 4);
    if (e >= E) return;
    int lane = (int)(t & 15);

    int   c = __ldg(&cols[e]);
    int   r = __ldg(&rows[e]);
    float v = __ldg(&vals[e]);

    float4 m = __ldg(&g_emb[src][(long long)c * DVEC + lane]);
    m.x *= v; m.y *= v; m.z *= v; m.w *= v;

    red_add_v4(&g_emb[dst][(long long)r * DVEC + lane], m);
}

// ---------------------------------------------------------------------------
// fuse: acc += g_emb[nb]; optionally zero the other buffer (next spmm target)
// ---------------------------------------------------------------------------
__global__ void lgcn_fuse(int nb, int do_zero) {
    int i = blockIdx.x * blockDim.x + threadIdx.x;
    if (i >= NN * DVEC) return;
    float4 a = g_acc[i];
    float4 n = g_emb[nb][i];
    a.x += n.x; a.y += n.y; a.z += n.z; a.w += n.w;
    g_acc[i] = a;
    if (do_zero) g_emb[1 - nb][i] = make_float4(0.f, 0.f, 0.f, 0.f);
}

// ---------------------------------------------------------------------------
// dot: one warp per (user, item) pair. gamma = dot(acc_u, acc_i) / 16
// ---------------------------------------------------------------------------
__global__ void lgcn_dot(const int* __restrict__ users,
                         const int* __restrict__ items,
                         float* __restrict__ out, int B) {
    int gt   = blockIdx.x * blockDim.x + threadIdx.x;
    int w    = gt >> 5;
    int lane = gt & 31;
    if (w >= B) return;

    int u  = __ldg(&users[w]);
    int it = __ldg(&items[w]);

    const float2* au = reinterpret_cast<const float2*>(&g_acc[(long long)u * DVEC]);
    const float2* ai = reinterpret_cast<const float2*>(&g_acc[(long long)(N_USERS + it) * DVEC]);

    float2 a = au[lane];
    float2 b = ai[lane];
    float s = a.x * b.x + a.y * b.y;

    #pragma unroll
    for (int off = 16; off > 0; off >>= 1)
        s += __shfl_xor_sync(0xFFFFFFFFu, s, off);

    if (lane == 0) out[w] = s * INV_SCALE;
}

// ---------------------------------------------------------------------------
// kernel_launch
// Inputs: 0 users(int32,B) 1 items(int32,B) 2 user_emb(f32) 3 item_emb(f32)
//         4 adj_rows(int32,NNZ) 5 adj_cols(int32,NNZ) 6 adj_vals(f32,NNZ)
// Output: gamma (f32, B)
// ---------------------------------------------------------------------------
extern "C" void kernel_launch(void* const* d_in, const int* in_sizes, int n_in,
                              void* d_out, int out_size) {
    const int*   users    = (const int*)  d_in[0];
    const int*   items    = (const int*)  d_in[1];
    const float* user_emb = (const float*)d_in[2];
    const float* item_emb = (const float*)d_in[3];
    const int*   rows     = (const int*)  d_in[4];
    const int*   cols     = (const int*)  d_in[5];
    const float* vals     = (const float*)d_in[6];
    float*       out      = (float*)      d_out;

    const int E = in_sizes[4];
    const int B = in_sizes[0];

    const int elemN   = NN * DVEC;
    const int TPB     = 256;
    const int gInit   = (elemN + TPB - 1) / TPB;
    const long long spmmThreads = (long long)E * 16;
    const int gSpmm   = (int)((spmmThreads + TPB - 1) / TPB);
    const int gDot    = (B * 32 + TPB - 1) / TPB;

    lgcn_init<<<gInit, TPB>>>(user_emb, item_emb);

    // layer 1: A -> B
    lgcn_spmm<<<gSpmm, TPB>>>(rows, cols, vals, E, 0, 1);
    lgcn_fuse<<<gInit, TPB>>>(1, 1);   // acc += B, zero A
    // layer 2: B -> A
    lgcn_spmm<<<gSpmm, TPB>>>(rows, cols, vals, E, 1, 0);
    lgcn_fuse<<<gInit, TPB>>>(0, 1);   // acc += A, zero B
    // layer 3: A -> B
    lgcn_spmm<<<gSpmm, TPB>>>(rows, cols, vals, E, 0, 1);
    lgcn_fuse<<<gInit, TPB>>>(1, 0);   // acc += B

    lgcn_dot<<<gDot, TPB>>>(users, items, out, B);
}

// round 2
// speedup vs baseline: 2.1269x; 2.1269x over previous
#include <cuda_runtime.h>
#include <cuda_bf16.h>

// LightGCN on GB300 — CSR gather-only SpMM.
//
// Per call:
//   1) init:   buf0 = concat(user_emb, item_emb); acc = buf0; zero row counters
//   2) CSR build: histogram(rows) -> exclusive scan -> scatter cols/vals by row
//   3) 3x spmm_csr: dst[r] = sum_e val[e]*src[col[e]];  acc[r] += dst[r]
//      (no atomics, no fuse, no zeroing)
//   4) dot: gamma[b] = dot(acc[u], acc[N_USERS+i]) / 16
//
// Embedding table (38.4 MB) is L2-resident; CSR halves L2 traffic vs COO+RED.

#define N_USERS 100000
#define M_ITEMS 50000
#define NN      (N_USERS + M_ITEMS)   // 150000
#define DVEC    16                    // D=64 floats = 16 float4
#define INV_SCALE (1.0f / 16.0f)      // 1/(LAYERS+1)^2
#define NNZ_MAX 4000000
#define SCAN_B  1024
#define NBLK_SCAN ((NN + SCAN_B - 1) / SCAN_B)   // 147

// Static device scratch (allocation-free).
__device__ float4 g_emb[2][NN * DVEC];   // ping-pong layer buffers
__device__ float4 g_acc[NN * DVEC];      // running sum
__device__ int    g_rowptr[NN + 1];
__device__ int    g_wpos[NN];            // counter, then write cursor
__device__ int    g_excl[NN];
__device__ int    g_bsum[256];
__device__ int    g_scol[NNZ_MAX];
__device__ float  g_sval[NNZ_MAX];

// ---------------------------------------------------------------------------
// init: buf0 = all_emb, acc = all_emb; zero row counters
// ---------------------------------------------------------------------------
__global__ void lgcn_init(const float* __restrict__ user_emb,
                          const float* __restrict__ item_emb) {
    int i = blockIdx.x * blockDim.x + threadIdx.x;   // float4 index
    if (i < NN) g_wpos[i] = 0;
    if (i >= NN * DVEC) return;
    float4 v;
    if (i < N_USERS * DVEC) {
        v = reinterpret_cast<const float4*>(user_emb)[i];
    } else {
        v = reinterpret_cast<const float4*>(item_emb)[i - N_USERS * DVEC];
    }
    g_emb[0][i] = v;
    g_acc[i]    = v;
}

// ---------------------------------------------------------------------------
// CSR build
// ---------------------------------------------------------------------------
__global__ void lgcn_hist(const int* __restrict__ rows, int E) {
    int i = blockIdx.x * blockDim.x + threadIdx.x;
    if (i < E) atomicAdd(&g_wpos[__ldg(&rows[i])], 1);
}

// Block-wide inclusive scan (Hillis-Steele) over counters; exclusive out.
__global__ void lgcn_scan1(int n) {
    __shared__ int s[SCAN_B];
    int i = blockIdx.x * SCAN_B + threadIdx.x;
    int v = (i < n) ? g_wpos[i] : 0;
    s[threadIdx.x] = v;
    __syncthreads();
    #pragma unroll
    for (int off = 1; off < SCAN_B; off <<= 1) {
        int t = (threadIdx.x >= off) ? s[threadIdx.x - off] : 0;
        __syncthreads();
        s[threadIdx.x] += t;
        __syncthreads();
    }
    int incl = s[threadIdx.x];
    if (i < n) g_excl[i] = incl - v;
    if (threadIdx.x == SCAN_B - 1) g_bsum[blockIdx.x] = incl;
}

__global__ void lgcn_scan2(int nb) {   // single block of 256
    __shared__ int s[256];
    int v = (threadIdx.x < nb) ? g_bsum[threadIdx.x] : 0;
    s[threadIdx.x] = v;
    __syncthreads();
    #pragma unroll
    for (int off = 1; off < 256; off <<= 1) {
        int t = (threadIdx.x >= off) ? s[threadIdx.x - off] : 0;
        __syncthreads();
        s[threadIdx.x] += t;
        __syncthreads();
    }
    if (threadIdx.x < nb) g_bsum[threadIdx.x] = s[threadIdx.x] - v;  // exclusive
}

__global__ void lgcn_scan3(int n, int E) {
    int i = blockIdx.x * blockDim.x + threadIdx.x;
    if (i >= n) return;
    int p = g_excl[i] + g_bsum[i / SCAN_B];
    g_rowptr[i] = p;
    g_wpos[i]   = p;
    if (i == 0) g_rowptr[n] = E;
}

__global__ void lgcn_scatter(const int*   __restrict__ rows,
                             const int*   __restrict__ cols,
                             const float* __restrict__ vals, int E) {
    int i = blockIdx.x * blockDim.x + threadIdx.x;
    if (i >= E) return;
    int r   = __ldg(&rows[i]);
    int pos = atomicAdd(&g_wpos[r], 1);
    g_scol[pos] = __ldg(&cols[i]);
    g_sval[pos] = __ldg(&vals[i]);
}

// ---------------------------------------------------------------------------
// CSR SpMM: one warp per row. Lanes split into two halves; each half walks
// alternate edges; each lane owns one float4 component (coalesced 256B gather).
// Epilogue: dst[r] = sum (if needed for next layer), acc[r] += sum.
// ---------------------------------------------------------------------------
__global__ void lgcn_spmm_csr(int src, int dst, int writeDst) {
    int w = (blockIdx.x * blockDim.x + threadIdx.x) >> 5;   // row
    if (w >= NN) return;
    int lane = threadIdx.x & 31;
    int half = lane >> 4;
    int comp = lane & 15;

    int start = __ldg(&g_rowptr[w]);
    int end   = __ldg(&g_rowptr[w + 1]);

    const float4* __restrict__ S = g_emb[src];
    float4 a = make_float4(0.f, 0.f, 0.f, 0.f);

    #pragma unroll 4
    for (int e = start + half; e < end; e += 2) {
        int   c = __ldg(&g_scol[e]);
        float v = __ldg(&g_sval[e]);
        float4 x = __ldg(&S[c * DVEC + comp]);
        a.x += v * x.x; a.y += v * x.y; a.z += v * x.z; a.w += v * x.w;
    }

    // combine the two halves
    a.x += __shfl_xor_sync(0xFFFFFFFFu, a.x, 16);
    a.y += __shfl_xor_sync(0xFFFFFFFFu, a.y, 16);
    a.z += __shfl_xor_sync(0xFFFFFFFFu, a.z, 16);
    a.w += __shfl_xor_sync(0xFFFFFFFFu, a.w, 16);

    if (half == 0) {
        int o = w * DVEC + comp;
        if (writeDst) g_emb[dst][o] = a;
        float4 c0 = g_acc[o];
        c0.x += a.x; c0.y += a.y; c0.z += a.z; c0.w += a.w;
        g_acc[o] = c0;
    }
}

// ---------------------------------------------------------------------------
// dot: one warp per (user, item) pair
// ---------------------------------------------------------------------------
__global__ void lgcn_dot(const int* __restrict__ users,
                         const int* __restrict__ items,
                         float* __restrict__ out, int B) {
    int gt   = blockIdx.x * blockDim.x + threadIdx.x;
    int w    = gt >> 5;
    int lane = gt & 31;
    if (w >= B) return;

    int u  = __ldg(&users[w]);
    int it = __ldg(&items[w]);

    const float2* au = reinterpret_cast<const float2*>(&g_acc[u * DVEC]);
    const float2* ai = reinterpret_cast<const float2*>(&g_acc[(N_USERS + it) * DVEC]);

    float2 a = au[lane];
    float2 b = ai[lane];
    float s = a.x * b.x + a.y * b.y;

    #pragma unroll
    for (int off = 16; off > 0; off >>= 1)
        s += __shfl_xor_sync(0xFFFFFFFFu, s, off);

    if (lane == 0) out[w] = s * INV_SCALE;
}

// ---------------------------------------------------------------------------
// kernel_launch
// Inputs: 0 users(i32,B) 1 items(i32,B) 2 user_emb(f32) 3 item_emb(f32)
//         4 adj_rows(i32,NNZ) 5 adj_cols(i32,NNZ) 6 adj_vals(f32,NNZ)
// ---------------------------------------------------------------------------
extern "C" void kernel_launch(void* const* d_in, const int* in_sizes, int n_in,
                              void* d_out, int out_size) {
    const int*   users    = (const int*)  d_in[0];
    const int*   items    = (const int*)  d_in[1];
    const float* user_emb = (const float*)d_in[2];
    const float* item_emb = (const float*)d_in[3];
    const int*   rows     = (const int*)  d_in[4];
    const int*   cols     = (const int*)  d_in[5];
    const float* vals     = (const float*)d_in[6];
    float*       out      = (float*)      d_out;

    const int E = in_sizes[4];
    const int B = in_sizes[0];

    const int elemN = NN * DVEC;
    const int TPB   = 256;
    const int gInit = (elemN + TPB - 1) / TPB;
    const int gE    = (E + TPB - 1) / TPB;
    const int gN    = (NN + TPB - 1) / TPB;
    const int gSpmm = (NN * 32 + TPB - 1) / TPB;
    const int gDot  = (B * 32 + TPB - 1) / TPB;

    // init + CSR build
    lgcn_init<<<gInit, TPB>>>(user_emb, item_emb);
    lgcn_hist<<<gE, TPB>>>(rows, E);
    lgcn_scan1<<<NBLK_SCAN, SCAN_B>>>(NN);
    lgcn_scan2<<<1, 256>>>(NBLK_SCAN);
    lgcn_scan3<<<gN, TPB>>>(NN, E);
    lgcn_scatter<<<gE, TPB>>>(rows, cols, vals, E);

    // 3 propagation layers (ping-pong buffers, acc fused into epilogue)
    lgcn_spmm_csr<<<gSpmm, TPB>>>(0, 1, 1);
    lgcn_spmm_csr<<<gSpmm, TPB>>>(1, 0, 1);
    lgcn_spmm_csr<<<gSpmm, TPB>>>(0, 1, 0);   // last layer: acc only

    lgcn_dot<<<gDot, TPB>>>(users, items, out, B);
}